// round 15
// baseline (speedup 1.0000x reference)
#include <cuda_runtime.h>
#include <cuda_bf16.h>
#include <cstdint>
#include <cstddef>

// ---------------- scratch (device globals; no allocation allowed) ----------------
__device__ __nv_bfloat16 g_h_hi [8192u * 1024u];
__device__ __nv_bfloat16 g_h_lo [8192u * 1024u];
__device__ __nv_bfloat16 g_qkv_hi[8192u * 3072u]; // Q|K|V concat along N
__device__ __nv_bfloat16 g_qkv_lo[8192u * 3072u];
__device__ __nv_bfloat16 g_wqkv_hi[1024u * 3072u];
__device__ __nv_bfloat16 g_wqkv_lo[1024u * 3072u];
__device__ __nv_bfloat16 g_wc_hi[1024u * 1024u];
__device__ __nv_bfloat16 g_wc_lo[1024u * 1024u];
__device__ __nv_bfloat16 g_w1_hi[1024u * 4096u];
__device__ __nv_bfloat16 g_w1_lo[1024u * 4096u];
__device__ __nv_bfloat16 g_ctx_hi[8192u * 1024u];
__device__ __nv_bfloat16 g_ctx_lo[8192u * 1024u];
__device__ float g_t1 [8192u * 1024u];            // ctx@Wc fp32 (pre-LN1)
__device__ __nv_bfloat16 g_t1_hi[8192u * 1024u];  // LN1 output split
__device__ __nv_bfloat16 g_t1_lo[8192u * 1024u];
__device__ float g_mlp[8192ull * 4096ull];
__device__ unsigned g_mask[1u << 22];             // 2^27 dropout bits packed

// ---------------- helpers ----------------
__device__ __forceinline__ unsigned rotl32(unsigned x, int r) { return __funnelshift_l(x, x, r); }
__device__ __forceinline__ unsigned smem_u32p(const void* p) {
    return (unsigned)__cvta_generic_to_shared(p);
}
__device__ __forceinline__ void ldsm4(uint32_t& r0, uint32_t& r1, uint32_t& r2, uint32_t& r3, unsigned a) {
    asm volatile("ldmatrix.sync.aligned.m8n8.x4.shared.b16 {%0,%1,%2,%3},[%4];"
                 : "=r"(r0), "=r"(r1), "=r"(r2), "=r"(r3) : "r"(a));
}
__device__ __forceinline__ void ldsm4t(uint32_t& r0, uint32_t& r1, uint32_t& r2, uint32_t& r3, unsigned a) {
    asm volatile("ldmatrix.sync.aligned.m8n8.x4.trans.shared.b16 {%0,%1,%2,%3},[%4];"
                 : "=r"(r0), "=r"(r1), "=r"(r2), "=r"(r3) : "r"(a));
}
__device__ __forceinline__ void mma16816(float* c, const uint32_t* a, uint32_t b0, uint32_t b1) {
    asm volatile("mma.sync.aligned.m16n8k16.row.col.f32.bf16.bf16.f32 "
                 "{%0,%1,%2,%3},{%4,%5,%6,%7},{%8,%9},{%0,%1,%2,%3};"
                 : "+f"(c[0]), "+f"(c[1]), "+f"(c[2]), "+f"(c[3])
                 : "r"(a[0]), "r"(a[1]), "r"(a[2]), "r"(a[3]), "r"(b0), "r"(b1));
}
__device__ __forceinline__ void split_bf16(float x, __nv_bfloat16& h, __nv_bfloat16& l) {
    h = __float2bfloat16_rn(x);
    l = __float2bfloat16_rn(x - __bfloat162float(h));
}
__device__ __forceinline__ void cp16(unsigned s, const void* g) {
    asm volatile("cp.async.cg.shared.global [%0], [%1], 16;" :: "r"(s), "l"(g));
}
__device__ __forceinline__ void cp_commit() {
    asm volatile("cp.async.commit_group;" ::: "memory");
}
__device__ __forceinline__ void cp_wait0() {
    asm volatile("cp.async.wait_group 0;" ::: "memory");
}
__device__ __forceinline__ void bar_pair(int id) {
    asm volatile("bar.sync %0, 64;" :: "r"(id) : "memory");
}

// ---------------- threefry dropout mask (exact JAX bernoulli, partitionable path) ----------------
// Launched in halves: base = 0 covers bh 0..63, base = 2^26 covers bh 64..127.
__global__ void __launch_bounds__(256) dropout_mask_kernel(unsigned* __restrict__ mask,
                                                           unsigned base) {
    const unsigned i = base + blockIdx.x * 256u + threadIdx.x;
    const unsigned k0 = 0u, k1 = 42u, k2 = 0x1BD11BDAu ^ 0u ^ 42u;
    unsigned x0 = 0u + k0;
    unsigned x1 = i + k1;
#define TF_ROUND(r) { x0 += x1; x1 = rotl32(x1, r); x1 ^= x0; }
    TF_ROUND(13) TF_ROUND(15) TF_ROUND(26) TF_ROUND(6)
    x0 += k1; x1 += k2 + 1u;
    TF_ROUND(17) TF_ROUND(29) TF_ROUND(16) TF_ROUND(24)
    x0 += k2; x1 += k0 + 2u;
    TF_ROUND(13) TF_ROUND(15) TF_ROUND(26) TF_ROUND(6)
    x0 += k0; x1 += k1 + 3u;
    TF_ROUND(17) TF_ROUND(29) TF_ROUND(16) TF_ROUND(24)
    x0 += k1; x1 += k2 + 4u;
    TF_ROUND(13) TF_ROUND(15) TF_ROUND(26) TF_ROUND(6)
    x0 += k2; x1 += k0 + 5u;
#undef TF_ROUND
    const unsigned bits = x0 ^ x1;
    const float u = __uint_as_float((bits >> 9) | 0x3f800000u) - 1.0f;
    const unsigned w = __ballot_sync(0xffffffffu, u < 0.9f);
    if ((threadIdx.x & 31u) == 0u) mask[i >> 5] = w;
}

// ---------------- fp32 -> (hi,lo) bf16 split, strided destination ----------------
__global__ void __launch_bounds__(256) convert_split_kernel(
    const float* __restrict__ src, __nv_bfloat16* __restrict__ hi,
    __nv_bfloat16* __restrict__ lo, int rows, int cols, int dst_stride)
{
    const unsigned t = blockIdx.x * 256u + threadIdx.x;
    const unsigned n4 = (unsigned)(rows * cols) >> 2;
    if (t >= n4) return;
    const unsigned e = t << 2;
    const int r = e / cols, c = e % cols;
    float4 v = *(const float4*)(src + e);
    __nv_bfloat16 h0, h1, h2, h3, l0, l1, l2, l3;
    split_bf16(v.x, h0, l0); split_bf16(v.y, h1, l1);
    split_bf16(v.z, h2, l2); split_bf16(v.w, h3, l3);
    __nv_bfloat162* ph = (__nv_bfloat162*)(hi + (size_t)r * dst_stride + c);
    __nv_bfloat162* pl = (__nv_bfloat162*)(lo + (size_t)r * dst_stride + c);
    ph[0] = __halves2bfloat162(h0, h1); ph[1] = __halves2bfloat162(h2, h3);
    pl[0] = __halves2bfloat162(l0, l1); pl[1] = __halves2bfloat162(l2, l3);
}

// ================= tensor-core GEMM, 128x128 block tile, cp.async pipeline =================
#define GASZ (128 * 40)
#define GBSZ (32 * 136)
#define GSMEM_BYTES ((4 * GASZ + 4 * GBSZ) * 2)

__global__ void __launch_bounds__(256, 2) mma_gemm_bf16_kernel(
    const __nv_bfloat16* __restrict__ Ahg, const __nv_bfloat16* __restrict__ Alg,
    const __nv_bfloat16* __restrict__ Bhg, const __nv_bfloat16* __restrict__ Blg,
    const float* __restrict__ bias, float* __restrict__ Cf,
    __nv_bfloat16* __restrict__ Chg, __nv_bfloat16* __restrict__ Clg,
    int M, int N, int K, int relu)
{
    extern __shared__ __nv_bfloat16 gsm[];
    __nv_bfloat16* As_hi = gsm;
    __nv_bfloat16* As_lo = gsm + 2 * GASZ;
    __nv_bfloat16* Bs_hi = gsm + 4 * GASZ;
    __nv_bfloat16* Bs_lo = gsm + 4 * GASZ + 2 * GBSZ;

    const int tid = threadIdx.x;
    const int lane = tid & 31, w = tid >> 5;
    const int warpM = w >> 1, warpN = w & 1;
    const int row0 = blockIdx.y * 128, col0 = blockIdx.x * 128;

    const int mi = lane >> 3;
    unsigned a_off[2][2], b_off[4][2];
#pragma unroll
    for (int mt = 0; mt < 2; mt++)
#pragma unroll
        for (int kh = 0; kh < 2; kh++) {
            int ar = warpM * 32 + mt * 16 + (mi & 1) * 8 + (lane & 7);
            int ac = kh * 16 + (mi >> 1) * 8;
            a_off[mt][kh] = (unsigned)((ar * 40 + ac) * 2);
        }
#pragma unroll
    for (int ntp = 0; ntp < 4; ntp++)
#pragma unroll
        for (int kh = 0; kh < 2; kh++) {
            int kb = kh * 16 + (mi & 1) * 8 + (lane & 7);
            int nb = warpN * 64 + ntp * 16 + (mi >> 1) * 8;
            b_off[ntp][kh] = (unsigned)((kb * 136 + nb) * 2);
        }

    const unsigned ah_base = smem_u32p(As_hi);
    const unsigned al_base = smem_u32p(As_lo);
    const unsigned bh_base = smem_u32p(Bs_hi);
    const unsigned bl_base = smem_u32p(Bs_lo);

    float acc[2][8][4];
#pragma unroll
    for (int a = 0; a < 2; a++)
#pragma unroll
        for (int b = 0; b < 8; b++)
#pragma unroll
            for (int c = 0; c < 4; c++) acc[a][b][c] = 0.f;

    const int ua_row = tid >> 2;          // 0..63, +64
    const int ua_col = (tid & 3) * 8;
    const int ub_row0 = tid >> 4;         // 0..15, +16
    const int ub_col = (tid & 15) * 8;

    auto g_issue = [&](int kt, int tbuf) {
        const unsigned abh = ah_base + tbuf * (GASZ * 2);
        const unsigned abl = al_base + tbuf * (GASZ * 2);
        const unsigned bbh = bh_base + tbuf * (GBSZ * 2);
        const unsigned bbl = bl_base + tbuf * (GBSZ * 2);
#pragma unroll
        for (int i = 0; i < 2; i++) {
            const size_t ga = (size_t)(row0 + ua_row + i * 64) * K + kt * 32 + ua_col;
            const unsigned sa = (unsigned)(((ua_row + i * 64) * 40 + ua_col) * 2);
            cp16(abh + sa, Ahg + ga);
            cp16(abl + sa, Alg + ga);
        }
#pragma unroll
        for (int i = 0; i < 2; i++) {
            const size_t gb = (size_t)(kt * 32 + ub_row0 + i * 16) * N + col0 + ub_col;
            const unsigned sb = (unsigned)(((ub_row0 + i * 16) * 136 + ub_col) * 2);
            cp16(bbh + sb, Bhg + gb);
            cp16(bbl + sb, Blg + gb);
        }
        cp_commit();
    };

    auto compute = [&](int buf) {
        const unsigned abh = ah_base + buf * (GASZ * 2);
        const unsigned abl = al_base + buf * (GASZ * 2);
        const unsigned bbh = bh_base + buf * (GBSZ * 2);
        const unsigned bbl = bl_base + buf * (GBSZ * 2);
#pragma unroll
        for (int kh = 0; kh < 2; kh++) {
            uint32_t Ah[2][4], Al[2][4];
#pragma unroll
            for (int mt = 0; mt < 2; mt++) {
                ldsm4(Ah[mt][0], Ah[mt][1], Ah[mt][2], Ah[mt][3], abh + a_off[mt][kh]);
                ldsm4(Al[mt][0], Al[mt][1], Al[mt][2], Al[mt][3], abl + a_off[mt][kh]);
            }
#pragma unroll
            for (int ntp = 0; ntp < 4; ntp++) {
                uint32_t Bh[4], Bl[4];
                ldsm4t(Bh[0], Bh[1], Bh[2], Bh[3], bbh + b_off[ntp][kh]);
                ldsm4t(Bl[0], Bl[1], Bl[2], Bl[3], bbl + b_off[ntp][kh]);
#pragma unroll
                for (int mt = 0; mt < 2; mt++) {
                    float* c0 = acc[mt][ntp * 2];
                    float* c1 = acc[mt][ntp * 2 + 1];
                    mma16816(c0, Ah[mt], Bh[0], Bh[1]);
                    mma16816(c1, Ah[mt], Bh[2], Bh[3]);
                    mma16816(c0, Ah[mt], Bl[0], Bl[1]);
                    mma16816(c1, Ah[mt], Bl[2], Bl[3]);
                    mma16816(c0, Al[mt], Bh[0], Bh[1]);
                    mma16816(c1, Al[mt], Bh[2], Bh[3]);
                }
            }
        }
    };

    g_issue(0, 0);
    cp_wait0();
    __syncthreads();

    const int ktiles = K >> 5;
    int buf = 0;
    for (int t = 0; t < ktiles; t++) {
        const bool more = (t + 1 < ktiles);
        if (more) g_issue(t + 1, buf ^ 1);
        compute(buf);
        if (more) {
            cp_wait0();
            __syncthreads();
        }
        buf ^= 1;
    }

#pragma unroll
    for (int mt = 0; mt < 2; mt++) {
#pragma unroll
        for (int nt = 0; nt < 8; nt++) {
            const int row = row0 + warpM * 32 + mt * 16 + (lane >> 2);
            const int col = col0 + warpN * 64 + nt * 8 + (lane & 3) * 2;
            float bb0 = bias ? bias[col] : 0.f;
            float bb1 = bias ? bias[col + 1] : 0.f;
            float v0 = acc[mt][nt][0] + bb0, v1 = acc[mt][nt][1] + bb1;
            float v2 = acc[mt][nt][2] + bb0, v3 = acc[mt][nt][3] + bb1;
            if (relu) { v0 = fmaxf(v0, 0.f); v1 = fmaxf(v1, 0.f); v2 = fmaxf(v2, 0.f); v3 = fmaxf(v3, 0.f); }
            if (Cf) {
                float2 p0; p0.x = v0; p0.y = v1;
                float2 p1; p1.x = v2; p1.y = v3;
                *(float2*)(Cf + (size_t)row * N + col) = p0;
                *(float2*)(Cf + (size_t)(row + 8) * N + col) = p1;
            } else {
                __nv_bfloat16 h0, h1, h2, h3, l0, l1, l2, l3;
                split_bf16(v0, h0, l0); split_bf16(v1, h1, l1);
                split_bf16(v2, h2, l2); split_bf16(v3, h3, l3);
                *(__nv_bfloat162*)(Chg + (size_t)row * N + col) = __halves2bfloat162(h0, h1);
                *(__nv_bfloat162*)(Clg + (size_t)row * N + col) = __halves2bfloat162(l0, l1);
                *(__nv_bfloat162*)(Chg + (size_t)(row + 8) * N + col) = __halves2bfloat162(h2, h3);
                *(__nv_bfloat162*)(Clg + (size_t)(row + 8) * N + col) = __halves2bfloat162(l2, l3);
            }
        }
    }
}

// ---------------- fp32 SIMT SGEMM (embed: K=64), split bf16 output ----------------
__global__ void __launch_bounds__(256) sgemm_split_kernel(
    const float* __restrict__ A, const float* __restrict__ B,
    const float* __restrict__ bias,
    __nv_bfloat16* __restrict__ Chg, __nv_bfloat16* __restrict__ Clg,
    int M, int N, int K)
{
    __shared__ float As[2][8][128];
    __shared__ float Bs[2][8][128];

    const int tid = threadIdx.x;
    const int tx = tid & 15, ty = tid >> 4;
    const int row0 = blockIdx.y * 128;
    const int col0 = blockIdx.x * 128;

    const int arow = tid >> 1;
    const int acol = (tid & 1) << 2;
    const int brow = tid >> 5;
    const int bcol = (tid & 31) << 2;

    const float* Aptr = A + (size_t)(row0 + arow) * K + acol;
    const float* Bptr = B + (size_t)brow * N + col0 + bcol;

    float acc[8][8];
#pragma unroll
    for (int i = 0; i < 8; i++)
#pragma unroll
        for (int j = 0; j < 8; j++) acc[i][j] = 0.f;

    {
        float4 av = *(const float4*)Aptr;
        As[0][acol + 0][arow] = av.x; As[0][acol + 1][arow] = av.y;
        As[0][acol + 2][arow] = av.z; As[0][acol + 3][arow] = av.w;
        *(float4*)&Bs[0][brow][bcol] = *(const float4*)Bptr;
    }
    __syncthreads();

    const int nt = K >> 3;
    int buf = 0;
    for (int t = 0; t < nt; t++) {
        float4 av, bv;
        const bool more = (t + 1 < nt);
        if (more) {
            av = *(const float4*)(Aptr + (t + 1) * 8);
            bv = *(const float4*)(Bptr + (size_t)(t + 1) * 8 * N);
        }
#pragma unroll
        for (int kk = 0; kk < 8; kk++) {
            float a_frag[8], b_frag[8];
            float4 a0 = *(const float4*)&As[buf][kk][ty * 8];
            float4 a1 = *(const float4*)&As[buf][kk][ty * 8 + 4];
            float4 b0 = *(const float4*)&Bs[buf][kk][tx * 8];
            float4 b1 = *(const float4*)&Bs[buf][kk][tx * 8 + 4];
            a_frag[0]=a0.x; a_frag[1]=a0.y; a_frag[2]=a0.z; a_frag[3]=a0.w;
            a_frag[4]=a1.x; a_frag[5]=a1.y; a_frag[6]=a1.z; a_frag[7]=a1.w;
            b_frag[0]=b0.x; b_frag[1]=b0.y; b_frag[2]=b0.z; b_frag[3]=b0.w;
            b_frag[4]=b1.x; b_frag[5]=b1.y; b_frag[6]=b1.z; b_frag[7]=b1.w;
#pragma unroll
            for (int i = 0; i < 8; i++)
#pragma unroll
                for (int j = 0; j < 8; j++)
                    acc[i][j] += a_frag[i] * b_frag[j];
        }
        if (more) {
            buf ^= 1;
            As[buf][acol + 0][arow] = av.x; As[buf][acol + 1][arow] = av.y;
            As[buf][acol + 2][arow] = av.z; As[buf][acol + 3][arow] = av.w;
            *(float4*)&Bs[buf][brow][bcol] = bv;
            __syncthreads();
        }
    }

    float bias_r[8];
#pragma unroll
    for (int j = 0; j < 8; j++) bias_r[j] = bias ? bias[col0 + tx * 8 + j] : 0.f;

#pragma unroll
    for (int i = 0; i < 8; i++) {
        const int row = row0 + ty * 8 + i;
        __nv_bfloat16 hh[8], ll[8];
#pragma unroll
        for (int j = 0; j < 8; j++)
            split_bf16(acc[i][j] + bias_r[j], hh[j], ll[j]);
        __nv_bfloat162* ph = (__nv_bfloat162*)(Chg + (size_t)row * N + col0 + tx * 8);
        __nv_bfloat162* pl = (__nv_bfloat162*)(Clg + (size_t)row * N + col0 + tx * 8);
#pragma unroll
        for (int j = 0; j < 4; j++) {
            ph[j] = __halves2bfloat162(hh[2 * j], hh[2 * j + 1]);
            pl[j] = __halves2bfloat162(ll[2 * j], ll[2 * j + 1]);
        }
    }
}

// ================= flash attention (q64): cp.async double-buffered K/V, bh-sliced =================
#define AT_ST 72
#define AT_TSZ (64 * AT_ST)
#define KVBUF_B (4 * AT_TSZ * 2)                   // bytes per K/V buffer (Ksh,Ksl,Vh,Vl)
#define AT_HALVES (12 * AT_TSZ)                    // Q(2) + KV double (8) + P(2)
#define AT_SMEM_BYTES (AT_HALVES * 2 + 256 * 4)    // + pm[128], pe[128]

__global__ void __launch_bounds__(256, 2) attention_mma_kernel(
    const __nv_bfloat16* __restrict__ qkv_hi, const __nv_bfloat16* __restrict__ qkv_lo,
    const unsigned* __restrict__ mask,
    __nv_bfloat16* __restrict__ ctx_hi, __nv_bfloat16* __restrict__ ctx_lo,
    int bh_base)
{
    extern __shared__ char asmem[];
    __nv_bfloat16* bb = (__nv_bfloat16*)asmem;
    __nv_bfloat16* Qh  = bb;                        // tiles 0,1
    __nv_bfloat16* Ql  = bb + 1 * AT_TSZ;
    __nv_bfloat16* Ksh0 = bb + 2 * AT_TSZ;          // tiles 2..5 buf0, 6..9 buf1
    __nv_bfloat16* Ksl0 = bb + 3 * AT_TSZ;
    __nv_bfloat16* Vh0  = bb + 4 * AT_TSZ;
    __nv_bfloat16* Vl0  = bb + 5 * AT_TSZ;
    __nv_bfloat16* Ph  = bb + 10 * AT_TSZ;          // tiles 10,11
    __nv_bfloat16* Pl  = bb + 11 * AT_TSZ;
    float* pm = (float*)(asmem + AT_HALVES * 2);    // [64][2] partial max
    float* pe = pm + 128;                            // [64][2] partial esum

    const int tid = threadIdx.x, lane = tid & 31, w = tid >> 5;
    const int warpM = w & 3, warpN = w >> 2;
    const int bh = blockIdx.y + bh_base, b = bh >> 4, h = bh & 15;
    const int q0 = blockIdx.x << 6;
    const size_t rowbase = (size_t)b * 1024;
    const int qoff = h * 64, koff = 1024 + h * 64, voff = 2048 + h * 64;
    const int mi = lane >> 3;
    const int bar_id = warpM + 1;

    unsigned a_off[4];
    {
        const int arow = warpM * 16 + (mi & 1) * 8 + (lane & 7);
        const int acb = (mi >> 1) * 8;
#pragma unroll
        for (int kh = 0; kh < 4; kh++)
            a_off[kh] = (unsigned)((arow * AT_ST + kh * 16 + acb) * 2);
    }
    unsigned b_off[2][4];   // V path (ldsm4t on [k][d])
#pragma unroll
    for (int ntp = 0; ntp < 2; ntp++)
#pragma unroll
        for (int kh = 0; kh < 4; kh++) {
            int kb = kh * 16 + (mi & 1) * 8 + (lane & 7);
            int nb = warpN * 32 + ntp * 16 + (mi >> 1) * 8;
            b_off[ntp][kh] = (unsigned)((kb * AT_ST + nb) * 2);
        }
    unsigned bs_off[2][4];  // K path (non-trans ldsm4 on [n][k])
#pragma unroll
    for (int ntp = 0; ntp < 2; ntp++)
#pragma unroll
        for (int kh = 0; kh < 4; kh++) {
            int nrow = warpN * 32 + ntp * 16 + (mi >> 1) * 8 + (lane & 7);
            int kcol = kh * 16 + (mi & 1) * 8;
            bs_off[ntp][kh] = (unsigned)((nrow * AT_ST + kcol) * 2);
        }

    const unsigned qh_b = smem_u32p(Qh),  ql_b = smem_u32p(Ql);
    const unsigned kh_b0 = smem_u32p(Ksh0), kl_b0 = smem_u32p(Ksl0);
    const unsigned vh_b0 = smem_u32p(Vh0),  vl_b0 = smem_u32p(Vl0);
    const unsigned ph_b = smem_u32p(Ph),  pl_b = smem_u32p(Pl);

    // cp.async K/V issue: rows kq0, kq0+32 at cols d8..d8+7, into buffer tbuf
    const int kq0 = tid >> 3;
    const int d8 = (tid & 7) * 8;

    auto kv_issue = [&](int kt, int tbuf) {
        const int k0 = kt << 6;
        const unsigned kb_h = kh_b0 + tbuf * KVBUF_B;
        const unsigned kb_l = kl_b0 + tbuf * KVBUF_B;
        const unsigned vb_h = vh_b0 + tbuf * KVBUF_B;
        const unsigned vb_l = vl_b0 + tbuf * KVBUF_B;
#pragma unroll
        for (int i = 0; i < 2; i++) {
            const unsigned soff = (unsigned)(((kq0 + i * 32) * AT_ST + d8) * 2);
            const size_t ksrc = (rowbase + k0 + kq0 + i * 32) * 3072 + koff + d8;
            cp16(kb_h + soff, qkv_hi + ksrc);
            cp16(kb_l + soff, qkv_lo + ksrc);
            const size_t vsrc = (rowbase + k0 + kq0 + i * 32) * 3072 + voff + d8;
            cp16(vb_h + soff, qkv_hi + vsrc);
            cp16(vb_l + soff, qkv_lo + vsrc);
        }
        cp_commit();
    };

    // ---- prologue: issue K/V tile 0 (buf 0), load Q ----
    kv_issue(0, 0);
    for (int u = tid; u < 512; u += 256) {
        int q = u >> 3, qd8 = (u & 7) * 8;
        const size_t src = (rowbase + q0 + q) * 3072 + qoff + qd8;
        *(uint4*)(Qh + q * AT_ST + qd8) = *(const uint4*)(qkv_hi + src);
        *(uint4*)(Ql + q * AT_ST + qd8) = *(const uint4*)(qkv_lo + src);
    }
    cp_wait0();
    __syncthreads();

    float pacc[4][4];
#pragma unroll
    for (int j = 0; j < 4; j++)
#pragma unroll
        for (int c = 0; c < 4; c++) pacc[j][c] = 0.f;

    const int r0 = warpM * 16 + (lane >> 2);
    const int r1 = r0 + 8;
    float m_reg0 = -1e30f, m_reg1 = -1e30f;
    float l_reg0 = 0.f, l_reg1 = 0.f;
    const size_t mbase = (size_t)bh << 15;

    int buf = 0;
    for (int kt = 0; kt < 16; kt++) {
        const int k0 = kt << 6;
        const bool more = (kt + 1 < 16);

        // issue next K/V tile early (flies under S + softmax + PV)
        if (more) kv_issue(kt + 1, buf ^ 1);

        const unsigned kh_b = kh_b0 + buf * KVBUF_B;
        const unsigned kl_b = kl_b0 + buf * KVBUF_B;
        const unsigned vh_b = vh_b0 + buf * KVBUF_B;
        const unsigned vl_b = vl_b0 + buf * KVBUF_B;

        // ---- S = (Q * K^T) * 0.125 ----
        float sacc[4][4];
#pragma unroll
        for (int j = 0; j < 4; j++)
#pragma unroll
            for (int c = 0; c < 4; c++) sacc[j][c] = 0.f;
#pragma unroll
        for (int kh = 0; kh < 4; kh++) {
            uint32_t Ah[4], Al[4];
            ldsm4(Ah[0], Ah[1], Ah[2], Ah[3], qh_b + a_off[kh]);
            ldsm4(Al[0], Al[1], Al[2], Al[3], ql_b + a_off[kh]);
#pragma unroll
            for (int ntp = 0; ntp < 2; ntp++) {
                uint32_t Bh[4], Bl[4];
                ldsm4(Bh[0], Bh[1], Bh[2], Bh[3], kh_b + bs_off[ntp][kh]);
                ldsm4(Bl[0], Bl[1], Bl[2], Bl[3], kl_b + bs_off[ntp][kh]);
                float* c0 = sacc[ntp * 2];
                float* c1 = sacc[ntp * 2 + 1];
                mma16816(c0, Ah, Bh[0], Bh[1]);
                mma16816(c1, Ah, Bh[2], Bh[3]);
                mma16816(c0, Ah, Bl[0], Bl[1]);
                mma16816(c1, Ah, Bl[2], Bl[3]);
                mma16816(c0, Al, Bh[0], Bh[1]);
                mma16816(c1, Al, Bh[2], Bh[3]);
            }
        }
#pragma unroll
        for (int j = 0; j < 4; j++)
#pragma unroll
            for (int c = 0; c < 4; c++) sacc[j][c] *= 0.125f;

        // ---- row max (quad shfl + pair smem exchange) ----
        float mx0 = -1e30f, mx1 = -1e30f;
#pragma unroll
        for (int j = 0; j < 4; j++) {
            mx0 = fmaxf(mx0, fmaxf(sacc[j][0], sacc[j][1]));
            mx1 = fmaxf(mx1, fmaxf(sacc[j][2], sacc[j][3]));
        }
        mx0 = fmaxf(mx0, __shfl_xor_sync(0xffffffffu, mx0, 1));
        mx0 = fmaxf(mx0, __shfl_xor_sync(0xffffffffu, mx0, 2));
        mx1 = fmaxf(mx1, __shfl_xor_sync(0xffffffffu, mx1, 1));
        mx1 = fmaxf(mx1, __shfl_xor_sync(0xffffffffu, mx1, 2));
        if ((lane & 3) == 0) {
            pm[r0 * 2 + warpN] = mx0;
            pm[r1 * 2 + warpN] = mx1;
        }
        bar_pair(bar_id);                              // (b) pair-local

        const float mnew0 = fmaxf(m_reg0, fmaxf(pm[r0 * 2], pm[r0 * 2 + 1]));
        const float mnew1 = fmaxf(m_reg1, fmaxf(pm[r1 * 2], pm[r1 * 2 + 1]));
        const float fc0 = __expf(m_reg0 - mnew0);
        const float fc1 = __expf(m_reg1 - mnew1);
        m_reg0 = mnew0; m_reg1 = mnew1;

        const unsigned mw0 = mask[mbase + ((size_t)(q0 + r0) << 5) + (unsigned)((k0 >> 5) + warpN)];
        const unsigned mw1 = mask[mbase + ((size_t)(q0 + r1) << 5) + (unsigned)((k0 >> 5) + warpN)];

        float es0 = 0.f, es1 = 0.f;
#pragma unroll
        for (int j = 0; j < 4; j++) {
            const int cb = j * 8 + (lane & 3) * 2;
            float e0 = __expf(sacc[j][0] - mnew0);
            float e1 = __expf(sacc[j][1] - mnew0);
            es0 += e0 + e1;
            float p0 = ((mw0 >> cb) & 1u) ? e0 * (1.0f / 0.9f) : 0.f;
            float p1 = ((mw0 >> (cb + 1)) & 1u) ? e1 * (1.0f / 0.9f) : 0.f;
            __nv_bfloat16 h0, l0, h1, l1;
            split_bf16(p0, h0, l0); split_bf16(p1, h1, l1);
            *(__nv_bfloat162*)(Ph + r0 * AT_ST + warpN * 32 + cb) = __halves2bfloat162(h0, h1);
            *(__nv_bfloat162*)(Pl + r0 * AT_ST + warpN * 32 + cb) = __halves2bfloat162(l0, l1);

            float e2 = __expf(sacc[j][2] - mnew1);
            float e3 = __expf(sacc[j][3] - mnew1);
            es1 += e2 + e3;
            float p2 = ((mw1 >> cb) & 1u) ? e2 * (1.0f / 0.9f) : 0.f;
            float p3 = ((mw1 >> (cb + 1)) & 1u) ? e3 * (1.0f / 0.9f) : 0.f;
            __nv_bfloat16 h2, l2, h3, l3;
            split_bf16(p2, h2, l2); split_bf16(p3, h3, l3);
            *(__nv_bfloat162*)(Ph + r1 * AT_ST + warpN * 32 + cb) = __halves2bfloat162(h2, h3);
            *(__nv_bfloat162*)(Pl + r1 * AT_ST + warpN * 32 + cb) = __halves2bfloat162(l2, l3);
        }
        es0 += __shfl_xor_sync(0xffffffffu, es0, 1);
        es0 += __shfl_xor_sync(0xffffffffu, es0, 2);
        es1 += __shfl_xor_sync(0xffffffffu, es1, 1);
        es1 += __shfl_xor_sync(0xffffffffu, es1, 2);
        if ((lane & 3) == 0) {
            pe[r0 * 2 + warpN] = es0;
            pe[r1 * 2 + warpN] = es1;
        }

        // rescale running ctx accumulators
#pragma unroll
        for (int j = 0; j < 4; j++) {
            pacc[j][0] *= fc0; pacc[j][1] *= fc0;
            pacc[j][2] *= fc1; pacc[j][3] *= fc1;
        }
        bar_pair(bar_id);                              // (c) pair-local: P + pe ready

        l_reg0 = l_reg0 * fc0 + pe[r0 * 2] + pe[r0 * 2 + 1];
        l_reg1 = l_reg1 * fc1 + pe[r1 * 2] + pe[r1 * 2 + 1];

        // ---- ctx += P * V ----
#pragma unroll
        for (int kh = 0; kh < 4; kh++) {
            uint32_t Ah[4], Al[4];
            ldsm4(Ah[0], Ah[1], Ah[2], Ah[3], ph_b + a_off[kh]);
            ldsm4(Al[0], Al[1], Al[2], Al[3], pl_b + a_off[kh]);
#pragma unroll
            for (int ntp = 0; ntp < 2; ntp++) {
                uint32_t Bh[4], Bl[4];
                ldsm4t(Bh[0], Bh[1], Bh[2], Bh[3], vh_b + b_off[ntp][kh]);
                ldsm4t(Bl[0], Bl[1], Bl[2], Bl[3], vl_b + b_off[ntp][kh]);
                float* c0 = pacc[ntp * 2];
                float* c1 = pacc[ntp * 2 + 1];
                mma16816(c0, Ah, Bh[0], Bh[1]);
                mma16816(c1, Ah, Bh[2], Bh[3]);
                mma16816(c0, Ah, Bl[0], Bl[1]);
                mma16816(c1, Ah, Bl[2], Bl[3]);
                mma16816(c0, Al, Bh[0], Bh[1]);
                mma16816(c1, Al, Bh[2], Bh[3]);
            }
        }

        if (more) {
            cp_wait0();                                // next tile landed
            __syncthreads();                           // block-wide: safe to consume buf^1 / overwrite buf
        }
        buf ^= 1;
    }

    // ---- epilogue ----
    {
        const float inv1 = 1.0f / l_reg0;
        const float inv2 = 1.0f / l_reg1;
        const int qg1 = q0 + r0, qg2 = q0 + r1;
#pragma unroll
        for (int j = 0; j < 4; j++) {
            const int col = warpN * 32 + j * 8 + (lane & 3) * 2;
            __nv_bfloat16 h0, h1, h2, h3, l0, l1, l2, l3;
            split_bf16(pacc[j][0] * inv1, h0, l0); split_bf16(pacc[j][1] * inv1, h1, l1);
            split_bf16(pacc[j][2] * inv2, h2, l2); split_bf16(pacc[j][3] * inv2, h3, l3);
            *(__nv_bfloat162*)(ctx_hi + (rowbase + qg1) * 1024 + qoff + col) = __halves2bfloat162(h0, h1);
            *(__nv_bfloat162*)(ctx_lo + (rowbase + qg1) * 1024 + qoff + col) = __halves2bfloat162(l0, l1);
            *(__nv_bfloat162*)(ctx_hi + (rowbase + qg2) * 1024 + qoff + col) = __halves2bfloat162(h2, h3);
            *(__nv_bfloat162*)(ctx_lo + (rowbase + qg2) * 1024 + qoff + col) = __halves2bfloat162(l2, l3);
        }
    }
}

// ---------------- layernorm (1024 cols, single gmem read) -> split bf16 ----------------
__global__ void __launch_bounds__(256) layernorm1024_split_kernel(
    const float* __restrict__ x, const float* __restrict__ g, const float* __restrict__ b,
    __nv_bfloat16* __restrict__ oh, __nv_bfloat16* __restrict__ ol)
{
    __shared__ float2 red[256];
    const int row = blockIdx.x, tid = threadIdx.x;
    const float* xr = x + (size_t)row * 1024;

    float4 v = *(const float4*)(xr + tid * 4);
    float s = v.x + v.y + v.z + v.w;
    float s2 = v.x * v.x + v.y * v.y + v.z * v.z + v.w * v.w;
    red[tid].x = s; red[tid].y = s2;
    __syncthreads();
    for (int o = 128; o; o >>= 1) {
        if (tid < o) { red[tid].x += red[tid + o].x; red[tid].y += red[tid + o].y; }
        __syncthreads();
    }
    const float mean = red[0].x * (1.0f / 1024.0f);
    const float var = red[0].y * (1.0f / 1024.0f) - mean * mean;
    const float inv = rsqrtf(var + 1e-5f);

    float4 gv = *(const float4*)(g + tid * 4);
    float4 bv = *(const float4*)(b + tid * 4);
    float o0 = (v.x - mean) * inv * gv.x + bv.x;
    float o1 = (v.y - mean) * inv * gv.y + bv.y;
    float o2 = (v.z - mean) * inv * gv.z + bv.z;
    float o3 = (v.w - mean) * inv * gv.w + bv.w;
    __nv_bfloat16 h0, h1, h2, h3, l0, l1, l2, l3;
    split_bf16(o0, h0, l0); split_bf16(o1, h1, l1);
    split_bf16(o2, h2, l2); split_bf16(o3, h3, l3);
    __nv_bfloat162* ph = (__nv_bfloat162*)(oh + (size_t)row * 1024 + tid * 4);
    __nv_bfloat162* pl = (__nv_bfloat162*)(ol + (size_t)row * 1024 + tid * 4);
    ph[0] = __halves2bfloat162(h0, h1); ph[1] = __halves2bfloat162(h2, h3);
    pl[0] = __halves2bfloat162(l0, l1); pl[1] = __halves2bfloat162(l2, l3);
}

// ---------------- fused LN2 (4096) + W2 matvec + bias -> out ----------------
__global__ void __launch_bounds__(256) ln_mv_fused_kernel(
    const float* __restrict__ x, const float* __restrict__ g, const float* __restrict__ b,
    const float* __restrict__ w2, const float* __restrict__ b2, float* __restrict__ out)
{
    __shared__ float2 red[256];
    __shared__ float redf[256];
    const int row = blockIdx.x, tid = threadIdx.x;
    const float* xr = x + (size_t)row * 4096;

    float xs[16];
    float s = 0.f, s2 = 0.f;
#pragma unroll
    for (int k = 0; k < 16; k++) {
        float v = xr[tid + k * 256];
        xs[k] = v;
        s += v;
        s2 += v * v;
    }
    red[tid].x = s; red[tid].y = s2;
    __syncthreads();
    for (int o = 128; o; o >>= 1) {
        if (tid < o) { red[tid].x += red[tid + o].x; red[tid].y += red[tid + o].y; }
        __syncthreads();
    }
    const float mean = red[0].x * (1.0f / 4096.0f);
    const float var = red[0].y * (1.0f / 4096.0f) - mean * mean;
    const float inv = rsqrtf(var + 1e-5f);
    __syncthreads();

    float acc = 0.f;
#pragma unroll
    for (int k = 0; k < 16; k++) {
        const int c = tid + k * 256;
        float v = (xs[k] - mean) * inv * g[c] + b[c];
        acc += v * w2[c];
    }
    redf[tid] = acc;
    __syncthreads();
    for (int o = 128; o; o >>= 1) {
        if (tid < o) redf[tid] += redf[tid + o];
        __syncthreads();
    }
    if (tid == 0) out[row] = redf[0] + b2[0];
}

// ---------------- launch ----------------
extern "C" void kernel_launch(void* const* d_in, const int* in_sizes, int n_in,
                              void* d_out, int out_size)
{
    (void)in_sizes; (void)n_in; (void)out_size;
    const float* x     = (const float*)d_in[0];
    const float* W_emb = (const float*)d_in[2];
    const float* b_emb = (const float*)d_in[3];
    const float* Wq    = (const float*)d_in[4];
    const float* Wk    = (const float*)d_in[5];
    const float* Wv    = (const float*)d_in[6];
    const float* Wc    = (const float*)d_in[7];
    const float* b_c   = (const float*)d_in[8];
    const float* ln1_g = (const float*)d_in[9];
    const float* ln1_b = (const float*)d_in[10];
    const float* W1    = (const float*)d_in[11];
    const float* b1    = (const float*)d_in[12];
    const float* ln2_g = (const float*)d_in[13];
    const float* ln2_b = (const float*)d_in[14];
    const float* W2    = (const float*)d_in[15];
    const float* b2    = (const float*)d_in[16];

    float *t1, *mlp; unsigned* mask;
    __nv_bfloat16 *h_hi, *h_lo, *qkv_hi, *qkv_lo, *wqkv_hi, *wqkv_lo,
                  *wc_hi, *wc_lo, *w1_hi, *w1_lo, *ctx_hi, *ctx_lo, *t1_hi, *t1_lo;
    cudaGetSymbolAddress((void**)&t1,   g_t1);
    cudaGetSymbolAddress((void**)&mlp,  g_mlp);
    cudaGetSymbolAddress((void**)&mask, g_mask);
    cudaGetSymbolAddress((void**)&h_hi, g_h_hi);     cudaGetSymbolAddress((void**)&h_lo, g_h_lo);
    cudaGetSymbolAddress((void**)&qkv_hi, g_qkv_hi); cudaGetSymbolAddress((void**)&qkv_lo, g_qkv_lo);
    cudaGetSymbolAddress((void**)&wqkv_hi, g_wqkv_hi); cudaGetSymbolAddress((void**)&wqkv_lo, g_wqkv_lo);
    cudaGetSymbolAddress((void**)&wc_hi, g_wc_hi);   cudaGetSymbolAddress((void**)&wc_lo, g_wc_lo);
    cudaGetSymbolAddress((void**)&w1_hi, g_w1_hi);   cudaGetSymbolAddress((void**)&w1_lo, g_w1_lo);
    cudaGetSymbolAddress((void**)&ctx_hi, g_ctx_hi); cudaGetSymbolAddress((void**)&ctx_lo, g_ctx_lo);
    cudaGetSymbolAddress((void**)&t1_hi, g_t1_hi);   cudaGetSymbolAddress((void**)&t1_lo, g_t1_lo);

    static cudaStream_t s_mask = nullptr, s_w = nullptr;
    static cudaEvent_t ev_fork = nullptr, ev_mask0 = nullptr, ev_mask = nullptr, ev_w = nullptr;
    if (!s_mask) {
        cudaStreamCreateWithFlags(&s_mask, cudaStreamNonBlocking);
        cudaStreamCreateWithFlags(&s_w, cudaStreamNonBlocking);
        cudaEventCreateWithFlags(&ev_fork, cudaEventDisableTiming);
        cudaEventCreateWithFlags(&ev_mask0, cudaEventDisableTiming);
        cudaEventCreateWithFlags(&ev_mask, cudaEventDisableTiming);
        cudaEventCreateWithFlags(&ev_w, cudaEventDisableTiming);
    }

    cudaFuncSetAttribute(attention_mma_kernel, cudaFuncAttributeMaxDynamicSharedMemorySize, AT_SMEM_BYTES);
    cudaFuncSetAttribute(mma_gemm_bf16_kernel, cudaFuncAttributeMaxDynamicSharedMemorySize, GSMEM_BYTES);

    // fork side streams
    cudaEventRecord(ev_fork, 0);
    cudaStreamWaitEvent(s_mask, ev_fork, 0);
    cudaStreamWaitEvent(s_w, ev_fork, 0);

    // mask (ALU/issue-bound) in two halves on its own stream:
    // half 0 = bh 0..63 bits, half 1 = bh 64..127 bits
    dropout_mask_kernel<<<(1u << 26) / 256, 256, 0, s_mask>>>(mask, 0u);
    cudaEventRecord(ev_mask0, s_mask);
    dropout_mask_kernel<<<(1u << 26) / 256, 256, 0, s_mask>>>(mask, 1u << 26);
    cudaEventRecord(ev_mask, s_mask);

    // weight split/pack on s_w
    convert_split_kernel<<<1024, 256, 0, s_w>>>(Wq, wqkv_hi + 0,    wqkv_lo + 0,    1024, 1024, 3072);
    convert_split_kernel<<<1024, 256, 0, s_w>>>(Wk, wqkv_hi + 1024, wqkv_lo + 1024, 1024, 1024, 3072);
    convert_split_kernel<<<1024, 256, 0, s_w>>>(Wv, wqkv_hi + 2048, wqkv_lo + 2048, 1024, 1024, 3072);
    convert_split_kernel<<<1024, 256, 0, s_w>>>(Wc, wc_hi, wc_lo, 1024, 1024, 1024);
    convert_split_kernel<<<4096, 256, 0, s_w>>>(W1, w1_hi, w1_lo, 1024, 4096, 4096);
    cudaEventRecord(ev_w, s_w);

    // main chain: embed GEMM writes split bf16 directly
    sgemm_split_kernel<<<dim3(8, 64), 256>>>(x, W_emb, b_emb, h_hi, h_lo, 8192, 1024, 64);

    cudaStreamWaitEvent(0, ev_w, 0);
    // fused QKV GEMM -> split bf16 output
    mma_gemm_bf16_kernel<<<dim3(24, 64), 256, GSMEM_BYTES>>>(
        h_hi, h_lo, wqkv_hi, wqkv_lo, nullptr, nullptr, qkv_hi, qkv_lo, 8192, 3072, 1024, 0);

    // attention sliced by bh: first half only needs mask half 0 (overlaps mask half 1)
    cudaStreamWaitEvent(0, ev_mask0, 0);
    attention_mma_kernel<<<dim3(16, 64), 256, AT_SMEM_BYTES>>>(qkv_hi, qkv_lo, mask, ctx_hi, ctx_lo, 0);
    cudaStreamWaitEvent(0, ev_mask, 0);
    attention_mma_kernel<<<dim3(16, 64), 256, AT_SMEM_BYTES>>>(qkv_hi, qkv_lo, mask, ctx_hi, ctx_lo, 64);

    // output proj (fp32 out) + LN1 (single-read, split out)
    mma_gemm_bf16_kernel<<<dim3(8, 64), 256, GSMEM_BYTES>>>(
        ctx_hi, ctx_lo, wc_hi, wc_lo, b_c, t1, nullptr, nullptr, 8192, 1024, 1024, 0);
    layernorm1024_split_kernel<<<8192, 256>>>(t1, ln1_g, ln1_b, t1_hi, t1_lo);

    // MLP up + ReLU (fp32 out), fused LN2+head
    mma_gemm_bf16_kernel<<<dim3(32, 64), 256, GSMEM_BYTES>>>(
        t1_hi, t1_lo, w1_hi, w1_lo, b1, mlp, nullptr, nullptr, 8192, 4096, 1024, 1);
    ln_mv_fused_kernel<<<8192, 256>>>(mlp, ln2_g, ln2_b, W2, b2, (float*)d_out);
}

// round 17
// speedup vs baseline: 1.0678x; 1.0678x over previous
#include <cuda_runtime.h>
#include <cuda_bf16.h>
#include <cstdint>
#include <cstddef>

// ---------------- scratch (device globals; no allocation allowed) ----------------
__device__ __nv_bfloat16 g_h_hi [8192u * 1024u];
__device__ __nv_bfloat16 g_h_lo [8192u * 1024u];
__device__ __nv_bfloat16 g_qkv_hi[8192u * 3072u]; // Q|K|V concat along N
__device__ __nv_bfloat16 g_qkv_lo[8192u * 3072u];
__device__ __nv_bfloat16 g_wqkv_hi[1024u * 3072u];
__device__ __nv_bfloat16 g_wqkv_lo[1024u * 3072u];
__device__ __nv_bfloat16 g_wc_hi[1024u * 1024u];
__device__ __nv_bfloat16 g_wc_lo[1024u * 1024u];
__device__ __nv_bfloat16 g_w1_hi[1024u * 4096u];
__device__ __nv_bfloat16 g_w1_lo[1024u * 4096u];
__device__ __nv_bfloat16 g_ctx_hi[8192u * 1024u];
__device__ __nv_bfloat16 g_ctx_lo[8192u * 1024u];
__device__ float g_t1 [8192u * 1024u];            // ctx@Wc fp32 (pre-LN1)
__device__ __nv_bfloat16 g_t1_hi[8192u * 1024u];  // LN1 output split
__device__ __nv_bfloat16 g_t1_lo[8192u * 1024u];
__device__ float g_mlp[8192ull * 4096ull];
__device__ unsigned g_mask[1u << 22];             // 2^27 dropout bits packed

// ---------------- helpers ----------------
__device__ __forceinline__ unsigned rotl32(unsigned x, int r) { return __funnelshift_l(x, x, r); }
__device__ __forceinline__ unsigned smem_u32p(const void* p) {
    return (unsigned)__cvta_generic_to_shared(p);
}
__device__ __forceinline__ void ldsm4(uint32_t& r0, uint32_t& r1, uint32_t& r2, uint32_t& r3, unsigned a) {
    asm volatile("ldmatrix.sync.aligned.m8n8.x4.shared.b16 {%0,%1,%2,%3},[%4];"
                 : "=r"(r0), "=r"(r1), "=r"(r2), "=r"(r3) : "r"(a));
}
__device__ __forceinline__ void ldsm4t(uint32_t& r0, uint32_t& r1, uint32_t& r2, uint32_t& r3, unsigned a) {
    asm volatile("ldmatrix.sync.aligned.m8n8.x4.trans.shared.b16 {%0,%1,%2,%3},[%4];"
                 : "=r"(r0), "=r"(r1), "=r"(r2), "=r"(r3) : "r"(a));
}
__device__ __forceinline__ void mma16816(float* c, const uint32_t* a, uint32_t b0, uint32_t b1) {
    asm volatile("mma.sync.aligned.m16n8k16.row.col.f32.bf16.bf16.f32 "
                 "{%0,%1,%2,%3},{%4,%5,%6,%7},{%8,%9},{%0,%1,%2,%3};"
                 : "+f"(c[0]), "+f"(c[1]), "+f"(c[2]), "+f"(c[3])
                 : "r"(a[0]), "r"(a[1]), "r"(a[2]), "r"(a[3]), "r"(b0), "r"(b1));
}
__device__ __forceinline__ void split_bf16(float x, __nv_bfloat16& h, __nv_bfloat16& l) {
    h = __float2bfloat16_rn(x);
    l = __float2bfloat16_rn(x - __bfloat162float(h));
}
__device__ __forceinline__ void cp16(unsigned s, const void* g) {
    asm volatile("cp.async.cg.shared.global [%0], [%1], 16;" :: "r"(s), "l"(g));
}
__device__ __forceinline__ void cp_commit() {
    asm volatile("cp.async.commit_group;" ::: "memory");
}
__device__ __forceinline__ void cp_wait0() {
    asm volatile("cp.async.wait_group 0;" ::: "memory");
}
__device__ __forceinline__ void bar_pair(int id) {
    asm volatile("bar.sync %0, 64;" :: "r"(id) : "memory");
}

// ---------------- threefry dropout mask (exact JAX bernoulli, partitionable path) ----------------
// Launched in halves: base = 0 covers bh 0..63, base = 2^26 covers bh 64..127.
__global__ void __launch_bounds__(256) dropout_mask_kernel(unsigned* __restrict__ mask,
                                                           unsigned base) {
    const unsigned i = base + blockIdx.x * 256u + threadIdx.x;
    const unsigned k0 = 0u, k1 = 42u, k2 = 0x1BD11BDAu ^ 0u ^ 42u;
    unsigned x0 = 0u + k0;
    unsigned x1 = i + k1;
#define TF_ROUND(r) { x0 += x1; x1 = rotl32(x1, r); x1 ^= x0; }
    TF_ROUND(13) TF_ROUND(15) TF_ROUND(26) TF_ROUND(6)
    x0 += k1; x1 += k2 + 1u;
    TF_ROUND(17) TF_ROUND(29) TF_ROUND(16) TF_ROUND(24)
    x0 += k2; x1 += k0 + 2u;
    TF_ROUND(13) TF_ROUND(15) TF_ROUND(26) TF_ROUND(6)
    x0 += k0; x1 += k1 + 3u;
    TF_ROUND(17) TF_ROUND(29) TF_ROUND(16) TF_ROUND(24)
    x0 += k1; x1 += k2 + 4u;
    TF_ROUND(13) TF_ROUND(15) TF_ROUND(26) TF_ROUND(6)
    x0 += k2; x1 += k0 + 5u;
#undef TF_ROUND
    const unsigned bits = x0 ^ x1;
    const float u = __uint_as_float((bits >> 9) | 0x3f800000u) - 1.0f;
    const unsigned w = __ballot_sync(0xffffffffu, u < 0.9f);
    if ((threadIdx.x & 31u) == 0u) mask[i >> 5] = w;
}

// ---------------- all weight splits in ONE launch (5 segments) ----------------
__global__ void __launch_bounds__(256) convert_all_kernel(
    const float* __restrict__ Wq, const float* __restrict__ Wk, const float* __restrict__ Wv,
    const float* __restrict__ Wc, const float* __restrict__ W1,
    __nv_bfloat16* __restrict__ wqkv_hi, __nv_bfloat16* __restrict__ wqkv_lo,
    __nv_bfloat16* __restrict__ wc_hi, __nv_bfloat16* __restrict__ wc_lo,
    __nv_bfloat16* __restrict__ w1_hi, __nv_bfloat16* __restrict__ w1_lo)
{
    const int blk = blockIdx.x;
    const float* src; __nv_bfloat16 *hi, *lo; int cols, stride; unsigned lblk;
    if (blk < 1024)      { src = Wq; hi = wqkv_hi;        lo = wqkv_lo;        cols = 1024; stride = 3072; lblk = blk; }
    else if (blk < 2048) { src = Wk; hi = wqkv_hi + 1024; lo = wqkv_lo + 1024; cols = 1024; stride = 3072; lblk = blk - 1024; }
    else if (blk < 3072) { src = Wv; hi = wqkv_hi + 2048; lo = wqkv_lo + 2048; cols = 1024; stride = 3072; lblk = blk - 2048; }
    else if (blk < 4096) { src = Wc; hi = wc_hi; lo = wc_lo; cols = 1024; stride = 1024; lblk = blk - 3072; }
    else                 { src = W1; hi = w1_hi; lo = w1_lo; cols = 4096; stride = 4096; lblk = blk - 4096; }
    const unsigned t = lblk * 256u + threadIdx.x;
    const unsigned e = t << 2;
    const int r = e / cols, c = e % cols;
    float4 v = *(const float4*)(src + e);
    __nv_bfloat16 h0, h1, h2, h3, l0, l1, l2, l3;
    split_bf16(v.x, h0, l0); split_bf16(v.y, h1, l1);
    split_bf16(v.z, h2, l2); split_bf16(v.w, h3, l3);
    __nv_bfloat162* ph = (__nv_bfloat162*)(hi + (size_t)r * stride + c);
    __nv_bfloat162* pl = (__nv_bfloat162*)(lo + (size_t)r * stride + c);
    ph[0] = __halves2bfloat162(h0, h1); ph[1] = __halves2bfloat162(h2, h3);
    pl[0] = __halves2bfloat162(l0, l1); pl[1] = __halves2bfloat162(l2, l3);
}

// ================= tensor-core GEMM, 128x128 block tile, cp.async pipeline =================
#define GASZ (128 * 40)
#define GBSZ (32 * 136)
#define GSMEM_BYTES ((4 * GASZ + 4 * GBSZ) * 2)

__global__ void __launch_bounds__(256, 2) mma_gemm_bf16_kernel(
    const __nv_bfloat16* __restrict__ Ahg, const __nv_bfloat16* __restrict__ Alg,
    const __nv_bfloat16* __restrict__ Bhg, const __nv_bfloat16* __restrict__ Blg,
    const float* __restrict__ bias, float* __restrict__ Cf,
    __nv_bfloat16* __restrict__ Chg, __nv_bfloat16* __restrict__ Clg,
    int M, int N, int K, int relu)
{
    extern __shared__ __nv_bfloat16 gsm[];
    __nv_bfloat16* As_hi = gsm;
    __nv_bfloat16* As_lo = gsm + 2 * GASZ;
    __nv_bfloat16* Bs_hi = gsm + 4 * GASZ;
    __nv_bfloat16* Bs_lo = gsm + 4 * GASZ + 2 * GBSZ;

    const int tid = threadIdx.x;
    const int lane = tid & 31, w = tid >> 5;
    const int warpM = w >> 1, warpN = w & 1;
    const int row0 = blockIdx.y * 128, col0 = blockIdx.x * 128;

    const int mi = lane >> 3;
    unsigned a_off[2][2], b_off[4][2];
#pragma unroll
    for (int mt = 0; mt < 2; mt++)
#pragma unroll
        for (int kh = 0; kh < 2; kh++) {
            int ar = warpM * 32 + mt * 16 + (mi & 1) * 8 + (lane & 7);
            int ac = kh * 16 + (mi >> 1) * 8;
            a_off[mt][kh] = (unsigned)((ar * 40 + ac) * 2);
        }
#pragma unroll
    for (int ntp = 0; ntp < 4; ntp++)
#pragma unroll
        for (int kh = 0; kh < 2; kh++) {
            int kb = kh * 16 + (mi & 1) * 8 + (lane & 7);
            int nb = warpN * 64 + ntp * 16 + (mi >> 1) * 8;
            b_off[ntp][kh] = (unsigned)((kb * 136 + nb) * 2);
        }

    const unsigned ah_base = smem_u32p(As_hi);
    const unsigned al_base = smem_u32p(As_lo);
    const unsigned bh_base = smem_u32p(Bs_hi);
    const unsigned bl_base = smem_u32p(Bs_lo);

    float acc[2][8][4];
#pragma unroll
    for (int a = 0; a < 2; a++)
#pragma unroll
        for (int b = 0; b < 8; b++)
#pragma unroll
            for (int c = 0; c < 4; c++) acc[a][b][c] = 0.f;

    const int ua_row = tid >> 2;          // 0..63, +64
    const int ua_col = (tid & 3) * 8;
    const int ub_row0 = tid >> 4;         // 0..15, +16
    const int ub_col = (tid & 15) * 8;

    auto g_issue = [&](int kt, int tbuf) {
        const unsigned abh = ah_base + tbuf * (GASZ * 2);
        const unsigned abl = al_base + tbuf * (GASZ * 2);
        const unsigned bbh = bh_base + tbuf * (GBSZ * 2);
        const unsigned bbl = bl_base + tbuf * (GBSZ * 2);
#pragma unroll
        for (int i = 0; i < 2; i++) {
            const size_t ga = (size_t)(row0 + ua_row + i * 64) * K + kt * 32 + ua_col;
            const unsigned sa = (unsigned)(((ua_row + i * 64) * 40 + ua_col) * 2);
            cp16(abh + sa, Ahg + ga);
            cp16(abl + sa, Alg + ga);
        }
#pragma unroll
        for (int i = 0; i < 2; i++) {
            const size_t gb = (size_t)(kt * 32 + ub_row0 + i * 16) * N + col0 + ub_col;
            const unsigned sb = (unsigned)(((ub_row0 + i * 16) * 136 + ub_col) * 2);
            cp16(bbh + sb, Bhg + gb);
            cp16(bbl + sb, Blg + gb);
        }
        cp_commit();
    };

    auto compute = [&](int buf) {
        const unsigned abh = ah_base + buf * (GASZ * 2);
        const unsigned abl = al_base + buf * (GASZ * 2);
        const unsigned bbh = bh_base + buf * (GBSZ * 2);
        const unsigned bbl = bl_base + buf * (GBSZ * 2);
#pragma unroll
        for (int kh = 0; kh < 2; kh++) {
            uint32_t Ah[2][4], Al[2][4];
#pragma unroll
            for (int mt = 0; mt < 2; mt++) {
                ldsm4(Ah[mt][0], Ah[mt][1], Ah[mt][2], Ah[mt][3], abh + a_off[mt][kh]);
                ldsm4(Al[mt][0], Al[mt][1], Al[mt][2], Al[mt][3], abl + a_off[mt][kh]);
            }
#pragma unroll
            for (int ntp = 0; ntp < 4; ntp++) {
                uint32_t Bh[4], Bl[4];
                ldsm4t(Bh[0], Bh[1], Bh[2], Bh[3], bbh + b_off[ntp][kh]);
                ldsm4t(Bl[0], Bl[1], Bl[2], Bl[3], bbl + b_off[ntp][kh]);
#pragma unroll
                for (int mt = 0; mt < 2; mt++) {
                    float* c0 = acc[mt][ntp * 2];
                    float* c1 = acc[mt][ntp * 2 + 1];
                    mma16816(c0, Ah[mt], Bh[0], Bh[1]);
                    mma16816(c1, Ah[mt], Bh[2], Bh[3]);
                    mma16816(c0, Ah[mt], Bl[0], Bl[1]);
                    mma16816(c1, Ah[mt], Bl[2], Bl[3]);
                    mma16816(c0, Al[mt], Bh[0], Bh[1]);
                    mma16816(c1, Al[mt], Bh[2], Bh[3]);
                }
            }
        }
    };

    g_issue(0, 0);
    cp_wait0();
    __syncthreads();

    const int ktiles = K >> 5;
    int buf = 0;
    for (int t = 0; t < ktiles; t++) {
        const bool more = (t + 1 < ktiles);
        if (more) g_issue(t + 1, buf ^ 1);
        compute(buf);
        if (more) {
            cp_wait0();
            __syncthreads();
        }
        buf ^= 1;
    }

#pragma unroll
    for (int mt = 0; mt < 2; mt++) {
#pragma unroll
        for (int nt = 0; nt < 8; nt++) {
            const int row = row0 + warpM * 32 + mt * 16 + (lane >> 2);
            const int col = col0 + warpN * 64 + nt * 8 + (lane & 3) * 2;
            float bb0 = bias ? bias[col] : 0.f;
            float bb1 = bias ? bias[col + 1] : 0.f;
            float v0 = acc[mt][nt][0] + bb0, v1 = acc[mt][nt][1] + bb1;
            float v2 = acc[mt][nt][2] + bb0, v3 = acc[mt][nt][3] + bb1;
            if (relu) { v0 = fmaxf(v0, 0.f); v1 = fmaxf(v1, 0.f); v2 = fmaxf(v2, 0.f); v3 = fmaxf(v3, 0.f); }
            if (Cf) {
                float2 p0; p0.x = v0; p0.y = v1;
                float2 p1; p1.x = v2; p1.y = v3;
                *(float2*)(Cf + (size_t)row * N + col) = p0;
                *(float2*)(Cf + (size_t)(row + 8) * N + col) = p1;
            } else {
                __nv_bfloat16 h0, h1, h2, h3, l0, l1, l2, l3;
                split_bf16(v0, h0, l0); split_bf16(v1, h1, l1);
                split_bf16(v2, h2, l2); split_bf16(v3, h3, l3);
                *(__nv_bfloat162*)(Chg + (size_t)row * N + col) = __halves2bfloat162(h0, h1);
                *(__nv_bfloat162*)(Clg + (size_t)row * N + col) = __halves2bfloat162(l0, l1);
                *(__nv_bfloat162*)(Chg + (size_t)(row + 8) * N + col) = __halves2bfloat162(h2, h3);
                *(__nv_bfloat162*)(Clg + (size_t)(row + 8) * N + col) = __halves2bfloat162(l2, l3);
            }
        }
    }
}

// ---------------- fp32 SIMT SGEMM (embed: K=64), split bf16 output ----------------
__global__ void __launch_bounds__(256) sgemm_split_kernel(
    const float* __restrict__ A, const float* __restrict__ B,
    const float* __restrict__ bias,
    __nv_bfloat16* __restrict__ Chg, __nv_bfloat16* __restrict__ Clg,
    int M, int N, int K)
{
    __shared__ float As[2][8][128];
    __shared__ float Bs[2][8][128];

    const int tid = threadIdx.x;
    const int tx = tid & 15, ty = tid >> 4;
    const int row0 = blockIdx.y * 128;
    const int col0 = blockIdx.x * 128;

    const int arow = tid >> 1;
    const int acol = (tid & 1) << 2;
    const int brow = tid >> 5;
    const int bcol = (tid & 31) << 2;

    const float* Aptr = A + (size_t)(row0 + arow) * K + acol;
    const float* Bptr = B + (size_t)brow * N + col0 + bcol;

    float acc[8][8];
#pragma unroll
    for (int i = 0; i < 8; i++)
#pragma unroll
        for (int j = 0; j < 8; j++) acc[i][j] = 0.f;

    {
        float4 av = *(const float4*)Aptr;
        As[0][acol + 0][arow] = av.x; As[0][acol + 1][arow] = av.y;
        As[0][acol + 2][arow] = av.z; As[0][acol + 3][arow] = av.w;
        *(float4*)&Bs[0][brow][bcol] = *(const float4*)Bptr;
    }
    __syncthreads();

    const int nt = K >> 3;
    int buf = 0;
    for (int t = 0; t < nt; t++) {
        float4 av, bv;
        const bool more = (t + 1 < nt);
        if (more) {
            av = *(const float4*)(Aptr + (t + 1) * 8);
            bv = *(const float4*)(Bptr + (size_t)(t + 1) * 8 * N);
        }
#pragma unroll
        for (int kk = 0; kk < 8; kk++) {
            float a_frag[8], b_frag[8];
            float4 a0 = *(const float4*)&As[buf][kk][ty * 8];
            float4 a1 = *(const float4*)&As[buf][kk][ty * 8 + 4];
            float4 b0 = *(const float4*)&Bs[buf][kk][tx * 8];
            float4 b1 = *(const float4*)&Bs[buf][kk][tx * 8 + 4];
            a_frag[0]=a0.x; a_frag[1]=a0.y; a_frag[2]=a0.z; a_frag[3]=a0.w;
            a_frag[4]=a1.x; a_frag[5]=a1.y; a_frag[6]=a1.z; a_frag[7]=a1.w;
            b_frag[0]=b0.x; b_frag[1]=b0.y; b_frag[2]=b0.z; b_frag[3]=b0.w;
            b_frag[4]=b1.x; b_frag[5]=b1.y; b_frag[6]=b1.z; b_frag[7]=b1.w;
#pragma unroll
            for (int i = 0; i < 8; i++)
#pragma unroll
                for (int j = 0; j < 8; j++)
                    acc[i][j] += a_frag[i] * b_frag[j];
        }
        if (more) {
            buf ^= 1;
            As[buf][acol + 0][arow] = av.x; As[buf][acol + 1][arow] = av.y;
            As[buf][acol + 2][arow] = av.z; As[buf][acol + 3][arow] = av.w;
            *(float4*)&Bs[buf][brow][bcol] = bv;
            __syncthreads();
        }
    }

    float bias_r[8];
#pragma unroll
    for (int j = 0; j < 8; j++) bias_r[j] = bias ? bias[col0 + tx * 8 + j] : 0.f;

#pragma unroll
    for (int i = 0; i < 8; i++) {
        const int row = row0 + ty * 8 + i;
        __nv_bfloat16 hh[8], ll[8];
#pragma unroll
        for (int j = 0; j < 8; j++)
            split_bf16(acc[i][j] + bias_r[j], hh[j], ll[j]);
        __nv_bfloat162* ph = (__nv_bfloat162*)(Chg + (size_t)row * N + col0 + tx * 8);
        __nv_bfloat162* pl = (__nv_bfloat162*)(Clg + (size_t)row * N + col0 + tx * 8);
#pragma unroll
        for (int j = 0; j < 4; j++) {
            ph[j] = __halves2bfloat162(hh[2 * j], hh[2 * j + 1]);
            pl[j] = __halves2bfloat162(ll[2 * j], ll[2 * j + 1]);
        }
    }
}

// ================= flash attention (q64): cp.async double-buffered K/V, bh-sliced =================
#define AT_ST 72
#define AT_TSZ (64 * AT_ST)
#define KVBUF_B (4 * AT_TSZ * 2)                   // bytes per K/V buffer (Ksh,Ksl,Vh,Vl)
#define AT_HALVES (12 * AT_TSZ)                    // Q(2) + KV double (8) + P(2)
#define AT_SMEM_BYTES (AT_HALVES * 2 + 256 * 4)    // + pm[128], pe[128]

__global__ void __launch_bounds__(256, 2) attention_mma_kernel(
    const __nv_bfloat16* __restrict__ qkv_hi, const __nv_bfloat16* __restrict__ qkv_lo,
    const unsigned* __restrict__ mask,
    __nv_bfloat16* __restrict__ ctx_hi, __nv_bfloat16* __restrict__ ctx_lo,
    int bh_base)
{
    extern __shared__ char asmem[];
    __nv_bfloat16* bb = (__nv_bfloat16*)asmem;
    __nv_bfloat16* Qh  = bb;                        // tiles 0,1
    __nv_bfloat16* Ql  = bb + 1 * AT_TSZ;
    __nv_bfloat16* Ksh0 = bb + 2 * AT_TSZ;          // tiles 2..5 buf0, 6..9 buf1
    __nv_bfloat16* Ksl0 = bb + 3 * AT_TSZ;
    __nv_bfloat16* Vh0  = bb + 4 * AT_TSZ;
    __nv_bfloat16* Vl0  = bb + 5 * AT_TSZ;
    __nv_bfloat16* Ph  = bb + 10 * AT_TSZ;          // tiles 10,11
    __nv_bfloat16* Pl  = bb + 11 * AT_TSZ;
    float* pm = (float*)(asmem + AT_HALVES * 2);    // [64][2] partial max
    float* pe = pm + 128;                            // [64][2] partial esum

    const int tid = threadIdx.x, lane = tid & 31, w = tid >> 5;
    const int warpM = w & 3, warpN = w >> 2;
    const int bh = blockIdx.y + bh_base, b = bh >> 4, h = bh & 15;
    const int q0 = blockIdx.x << 6;
    const size_t rowbase = (size_t)b * 1024;
    const int qoff = h * 64, koff = 1024 + h * 64, voff = 2048 + h * 64;
    const int mi = lane >> 3;
    const int bar_id = warpM + 1;

    unsigned a_off[4];
    {
        const int arow = warpM * 16 + (mi & 1) * 8 + (lane & 7);
        const int acb = (mi >> 1) * 8;
#pragma unroll
        for (int kh = 0; kh < 4; kh++)
            a_off[kh] = (unsigned)((arow * AT_ST + kh * 16 + acb) * 2);
    }
    unsigned b_off[2][4];   // V path (ldsm4t on [k][d])
#pragma unroll
    for (int ntp = 0; ntp < 2; ntp++)
#pragma unroll
        for (int kh = 0; kh < 4; kh++) {
            int kb = kh * 16 + (mi & 1) * 8 + (lane & 7);
            int nb = warpN * 32 + ntp * 16 + (mi >> 1) * 8;
            b_off[ntp][kh] = (unsigned)((kb * AT_ST + nb) * 2);
        }
    unsigned bs_off[2][4];  // K path (non-trans ldsm4 on [n][k])
#pragma unroll
    for (int ntp = 0; ntp < 2; ntp++)
#pragma unroll
        for (int kh = 0; kh < 4; kh++) {
            int nrow = warpN * 32 + ntp * 16 + (mi >> 1) * 8 + (lane & 7);
            int kcol = kh * 16 + (mi & 1) * 8;
            bs_off[ntp][kh] = (unsigned)((nrow * AT_ST + kcol) * 2);
        }

    const unsigned qh_b = smem_u32p(Qh),  ql_b = smem_u32p(Ql);
    const unsigned kh_b0 = smem_u32p(Ksh0), kl_b0 = smem_u32p(Ksl0);
    const unsigned vh_b0 = smem_u32p(Vh0),  vl_b0 = smem_u32p(Vl0);
    const unsigned ph_b = smem_u32p(Ph),  pl_b = smem_u32p(Pl);

    // cp.async K/V issue: rows kq0, kq0+32 at cols d8..d8+7, into buffer tbuf
    const int kq0 = tid >> 3;
    const int d8 = (tid & 7) * 8;

    auto kv_issue = [&](int kt, int tbuf) {
        const int k0 = kt << 6;
        const unsigned kb_h = kh_b0 + tbuf * KVBUF_B;
        const unsigned kb_l = kl_b0 + tbuf * KVBUF_B;
        const unsigned vb_h = vh_b0 + tbuf * KVBUF_B;
        const unsigned vb_l = vl_b0 + tbuf * KVBUF_B;
#pragma unroll
        for (int i = 0; i < 2; i++) {
            const unsigned soff = (unsigned)(((kq0 + i * 32) * AT_ST + d8) * 2);
            const size_t ksrc = (rowbase + k0 + kq0 + i * 32) * 3072 + koff + d8;
            cp16(kb_h + soff, qkv_hi + ksrc);
            cp16(kb_l + soff, qkv_lo + ksrc);
            const size_t vsrc = (rowbase + k0 + kq0 + i * 32) * 3072 + voff + d8;
            cp16(vb_h + soff, qkv_hi + vsrc);
            cp16(vb_l + soff, qkv_lo + vsrc);
        }
        cp_commit();
    };

    // ---- prologue: issue K/V tile 0 (buf 0), load Q ----
    kv_issue(0, 0);
    for (int u = tid; u < 512; u += 256) {
        int q = u >> 3, qd8 = (u & 7) * 8;
        const size_t src = (rowbase + q0 + q) * 3072 + qoff + qd8;
        *(uint4*)(Qh + q * AT_ST + qd8) = *(const uint4*)(qkv_hi + src);
        *(uint4*)(Ql + q * AT_ST + qd8) = *(const uint4*)(qkv_lo + src);
    }
    cp_wait0();
    __syncthreads();

    float pacc[4][4];
#pragma unroll
    for (int j = 0; j < 4; j++)
#pragma unroll
        for (int c = 0; c < 4; c++) pacc[j][c] = 0.f;

    const int r0 = warpM * 16 + (lane >> 2);
    const int r1 = r0 + 8;
    float m_reg0 = -1e30f, m_reg1 = -1e30f;
    float l_reg0 = 0.f, l_reg1 = 0.f;
    const size_t mbase = (size_t)bh << 15;

    int buf = 0;
    for (int kt = 0; kt < 16; kt++) {
        const int k0 = kt << 6;
        const bool more = (kt + 1 < 16);

        // issue next K/V tile early (flies under S + softmax + PV)
        if (more) kv_issue(kt + 1, buf ^ 1);

        const unsigned kh_b = kh_b0 + buf * KVBUF_B;
        const unsigned kl_b = kl_b0 + buf * KVBUF_B;
        const unsigned vh_b = vh_b0 + buf * KVBUF_B;
        const unsigned vl_b = vl_b0 + buf * KVBUF_B;

        // ---- S = (Q * K^T) * 0.125 ----
        float sacc[4][4];
#pragma unroll
        for (int j = 0; j < 4; j++)
#pragma unroll
            for (int c = 0; c < 4; c++) sacc[j][c] = 0.f;
#pragma unroll
        for (int kh = 0; kh < 4; kh++) {
            uint32_t Ah[4], Al[4];
            ldsm4(Ah[0], Ah[1], Ah[2], Ah[3], qh_b + a_off[kh]);
            ldsm4(Al[0], Al[1], Al[2], Al[3], ql_b + a_off[kh]);
#pragma unroll
            for (int ntp = 0; ntp < 2; ntp++) {
                uint32_t Bh[4], Bl[4];
                ldsm4(Bh[0], Bh[1], Bh[2], Bh[3], kh_b + bs_off[ntp][kh]);
                ldsm4(Bl[0], Bl[1], Bl[2], Bl[3], kl_b + bs_off[ntp][kh]);
                float* c0 = sacc[ntp * 2];
                float* c1 = sacc[ntp * 2 + 1];
                mma16816(c0, Ah, Bh[0], Bh[1]);
                mma16816(c1, Ah, Bh[2], Bh[3]);
                mma16816(c0, Ah, Bl[0], Bl[1]);
                mma16816(c1, Ah, Bl[2], Bl[3]);
                mma16816(c0, Al, Bh[0], Bh[1]);
                mma16816(c1, Al, Bh[2], Bh[3]);
            }
        }
#pragma unroll
        for (int j = 0; j < 4; j++)
#pragma unroll
            for (int c = 0; c < 4; c++) sacc[j][c] *= 0.125f;

        // ---- row max (quad shfl + pair smem exchange) ----
        float mx0 = -1e30f, mx1 = -1e30f;
#pragma unroll
        for (int j = 0; j < 4; j++) {
            mx0 = fmaxf(mx0, fmaxf(sacc[j][0], sacc[j][1]));
            mx1 = fmaxf(mx1, fmaxf(sacc[j][2], sacc[j][3]));
        }
        mx0 = fmaxf(mx0, __shfl_xor_sync(0xffffffffu, mx0, 1));
        mx0 = fmaxf(mx0, __shfl_xor_sync(0xffffffffu, mx0, 2));
        mx1 = fmaxf(mx1, __shfl_xor_sync(0xffffffffu, mx1, 1));
        mx1 = fmaxf(mx1, __shfl_xor_sync(0xffffffffu, mx1, 2));
        if ((lane & 3) == 0) {
            pm[r0 * 2 + warpN] = mx0;
            pm[r1 * 2 + warpN] = mx1;
        }
        bar_pair(bar_id);                              // (b) pair-local

        const float mnew0 = fmaxf(m_reg0, fmaxf(pm[r0 * 2], pm[r0 * 2 + 1]));
        const float mnew1 = fmaxf(m_reg1, fmaxf(pm[r1 * 2], pm[r1 * 2 + 1]));
        const float fc0 = __expf(m_reg0 - mnew0);
        const float fc1 = __expf(m_reg1 - mnew1);
        m_reg0 = mnew0; m_reg1 = mnew1;

        const unsigned mw0 = mask[mbase + ((size_t)(q0 + r0) << 5) + (unsigned)((k0 >> 5) + warpN)];
        const unsigned mw1 = mask[mbase + ((size_t)(q0 + r1) << 5) + (unsigned)((k0 >> 5) + warpN)];

        float es0 = 0.f, es1 = 0.f;
#pragma unroll
        for (int j = 0; j < 4; j++) {
            const int cb = j * 8 + (lane & 3) * 2;
            float e0 = __expf(sacc[j][0] - mnew0);
            float e1 = __expf(sacc[j][1] - mnew0);
            es0 += e0 + e1;
            float p0 = ((mw0 >> cb) & 1u) ? e0 * (1.0f / 0.9f) : 0.f;
            float p1 = ((mw0 >> (cb + 1)) & 1u) ? e1 * (1.0f / 0.9f) : 0.f;
            __nv_bfloat16 h0, l0, h1, l1;
            split_bf16(p0, h0, l0); split_bf16(p1, h1, l1);
            *(__nv_bfloat162*)(Ph + r0 * AT_ST + warpN * 32 + cb) = __halves2bfloat162(h0, h1);
            *(__nv_bfloat162*)(Pl + r0 * AT_ST + warpN * 32 + cb) = __halves2bfloat162(l0, l1);

            float e2 = __expf(sacc[j][2] - mnew1);
            float e3 = __expf(sacc[j][3] - mnew1);
            es1 += e2 + e3;
            float p2 = ((mw1 >> cb) & 1u) ? e2 * (1.0f / 0.9f) : 0.f;
            float p3 = ((mw1 >> (cb + 1)) & 1u) ? e3 * (1.0f / 0.9f) : 0.f;
            __nv_bfloat16 h2, l2, h3, l3;
            split_bf16(p2, h2, l2); split_bf16(p3, h3, l3);
            *(__nv_bfloat162*)(Ph + r1 * AT_ST + warpN * 32 + cb) = __halves2bfloat162(h2, h3);
            *(__nv_bfloat162*)(Pl + r1 * AT_ST + warpN * 32 + cb) = __halves2bfloat162(l2, l3);
        }
        es0 += __shfl_xor_sync(0xffffffffu, es0, 1);
        es0 += __shfl_xor_sync(0xffffffffu, es0, 2);
        es1 += __shfl_xor_sync(0xffffffffu, es1, 1);
        es1 += __shfl_xor_sync(0xffffffffu, es1, 2);
        if ((lane & 3) == 0) {
            pe[r0 * 2 + warpN] = es0;
            pe[r1 * 2 + warpN] = es1;
        }

        // rescale running ctx accumulators
#pragma unroll
        for (int j = 0; j < 4; j++) {
            pacc[j][0] *= fc0; pacc[j][1] *= fc0;
            pacc[j][2] *= fc1; pacc[j][3] *= fc1;
        }
        bar_pair(bar_id);                              // (c) pair-local: P + pe ready

        l_reg0 = l_reg0 * fc0 + pe[r0 * 2] + pe[r0 * 2 + 1];
        l_reg1 = l_reg1 * fc1 + pe[r1 * 2] + pe[r1 * 2 + 1];

        // ---- ctx += P * V ----
#pragma unroll
        for (int kh = 0; kh < 4; kh++) {
            uint32_t Ah[4], Al[4];
            ldsm4(Ah[0], Ah[1], Ah[2], Ah[3], ph_b + a_off[kh]);
            ldsm4(Al[0], Al[1], Al[2], Al[3], pl_b + a_off[kh]);
#pragma unroll
            for (int ntp = 0; ntp < 2; ntp++) {
                uint32_t Bh[4], Bl[4];
                ldsm4t(Bh[0], Bh[1], Bh[2], Bh[3], vh_b + b_off[ntp][kh]);
                ldsm4t(Bl[0], Bl[1], Bl[2], Bl[3], vl_b + b_off[ntp][kh]);
                float* c0 = pacc[ntp * 2];
                float* c1 = pacc[ntp * 2 + 1];
                mma16816(c0, Ah, Bh[0], Bh[1]);
                mma16816(c1, Ah, Bh[2], Bh[3]);
                mma16816(c0, Ah, Bl[0], Bl[1]);
                mma16816(c1, Ah, Bl[2], Bl[3]);
                mma16816(c0, Al, Bh[0], Bh[1]);
                mma16816(c1, Al, Bh[2], Bh[3]);
            }
        }

        if (more) {
            cp_wait0();                                // next tile landed
            __syncthreads();                           // block-wide: safe to consume buf^1 / overwrite buf
        }
        buf ^= 1;
    }

    // ---- epilogue ----
    {
        const float inv1 = 1.0f / l_reg0;
        const float inv2 = 1.0f / l_reg1;
        const int qg1 = q0 + r0, qg2 = q0 + r1;
#pragma unroll
        for (int j = 0; j < 4; j++) {
            const int col = warpN * 32 + j * 8 + (lane & 3) * 2;
            __nv_bfloat16 h0, h1, h2, h3, l0, l1, l2, l3;
            split_bf16(pacc[j][0] * inv1, h0, l0); split_bf16(pacc[j][1] * inv1, h1, l1);
            split_bf16(pacc[j][2] * inv2, h2, l2); split_bf16(pacc[j][3] * inv2, h3, l3);
            *(__nv_bfloat162*)(ctx_hi + (rowbase + qg1) * 1024 + qoff + col) = __halves2bfloat162(h0, h1);
            *(__nv_bfloat162*)(ctx_lo + (rowbase + qg1) * 1024 + qoff + col) = __halves2bfloat162(l0, l1);
            *(__nv_bfloat162*)(ctx_hi + (rowbase + qg2) * 1024 + qoff + col) = __halves2bfloat162(h2, h3);
            *(__nv_bfloat162*)(ctx_lo + (rowbase + qg2) * 1024 + qoff + col) = __halves2bfloat162(l2, l3);
        }
    }
}

// ---------------- layernorm (1024 cols, single gmem read) -> split bf16 ----------------
__global__ void __launch_bounds__(256) layernorm1024_split_kernel(
    const float* __restrict__ x, const float* __restrict__ g, const float* __restrict__ b,
    __nv_bfloat16* __restrict__ oh, __nv_bfloat16* __restrict__ ol)
{
    __shared__ float2 red[256];
    const int row = blockIdx.x, tid = threadIdx.x;
    const float* xr = x + (size_t)row * 1024;

    float4 v = *(const float4*)(xr + tid * 4);
    float s = v.x + v.y + v.z + v.w;
    float s2 = v.x * v.x + v.y * v.y + v.z * v.z + v.w * v.w;
    red[tid].x = s; red[tid].y = s2;
    __syncthreads();
    for (int o = 128; o; o >>= 1) {
        if (tid < o) { red[tid].x += red[tid + o].x; red[tid].y += red[tid + o].y; }
        __syncthreads();
    }
    const float mean = red[0].x * (1.0f / 1024.0f);
    const float var = red[0].y * (1.0f / 1024.0f) - mean * mean;
    const float inv = rsqrtf(var + 1e-5f);

    float4 gv = *(const float4*)(g + tid * 4);
    float4 bv = *(const float4*)(b + tid * 4);
    float o0 = (v.x - mean) * inv * gv.x + bv.x;
    float o1 = (v.y - mean) * inv * gv.y + bv.y;
    float o2 = (v.z - mean) * inv * gv.z + bv.z;
    float o3 = (v.w - mean) * inv * gv.w + bv.w;
    __nv_bfloat16 h0, h1, h2, h3, l0, l1, l2, l3;
    split_bf16(o0, h0, l0); split_bf16(o1, h1, l1);
    split_bf16(o2, h2, l2); split_bf16(o3, h3, l3);
    __nv_bfloat162* ph = (__nv_bfloat162*)(oh + (size_t)row * 1024 + tid * 4);
    __nv_bfloat162* pl = (__nv_bfloat162*)(ol + (size_t)row * 1024 + tid * 4);
    ph[0] = __halves2bfloat162(h0, h1); ph[1] = __halves2bfloat162(h2, h3);
    pl[0] = __halves2bfloat162(l0, l1); pl[1] = __halves2bfloat162(l2, l3);
}

// ---------------- fused LN2 (4096) + W2 matvec + bias -> out ----------------
__global__ void __launch_bounds__(256) ln_mv_fused_kernel(
    const float* __restrict__ x, const float* __restrict__ g, const float* __restrict__ b,
    const float* __restrict__ w2, const float* __restrict__ b2, float* __restrict__ out)
{
    __shared__ float2 red[256];
    __shared__ float redf[256];
    const int row = blockIdx.x, tid = threadIdx.x;
    const float* xr = x + (size_t)row * 4096;

    float xs[16];
    float s = 0.f, s2 = 0.f;
#pragma unroll
    for (int k = 0; k < 16; k++) {
        float v = xr[tid + k * 256];
        xs[k] = v;
        s += v;
        s2 += v * v;
    }
    red[tid].x = s; red[tid].y = s2;
    __syncthreads();
    for (int o = 128; o; o >>= 1) {
        if (tid < o) { red[tid].x += red[tid + o].x; red[tid].y += red[tid + o].y; }
        __syncthreads();
    }
    const float mean = red[0].x * (1.0f / 4096.0f);
    const float var = red[0].y * (1.0f / 4096.0f) - mean * mean;
    const float inv = rsqrtf(var + 1e-5f);
    __syncthreads();

    float acc = 0.f;
#pragma unroll
    for (int k = 0; k < 16; k++) {
        const int c = tid + k * 256;
        float v = (xs[k] - mean) * inv * g[c] + b[c];
        acc += v * w2[c];
    }
    redf[tid] = acc;
    __syncthreads();
    for (int o = 128; o; o >>= 1) {
        if (tid < o) redf[tid] += redf[tid + o];
        __syncthreads();
    }
    if (tid == 0) out[row] = redf[0] + b2[0];
}

// ---------------- launch: two batch-half chains, chain B reuses s_w ----------------
extern "C" void kernel_launch(void* const* d_in, const int* in_sizes, int n_in,
                              void* d_out, int out_size)
{
    (void)in_sizes; (void)n_in; (void)out_size;
    const float* x     = (const float*)d_in[0];
    const float* W_emb = (const float*)d_in[2];
    const float* b_emb = (const float*)d_in[3];
    const float* Wq    = (const float*)d_in[4];
    const float* Wk    = (const float*)d_in[5];
    const float* Wv    = (const float*)d_in[6];
    const float* Wc    = (const float*)d_in[7];
    const float* b_c   = (const float*)d_in[8];
    const float* ln1_g = (const float*)d_in[9];
    const float* ln1_b = (const float*)d_in[10];
    const float* W1    = (const float*)d_in[11];
    const float* b1    = (const float*)d_in[12];
    const float* ln2_g = (const float*)d_in[13];
    const float* ln2_b = (const float*)d_in[14];
    const float* W2    = (const float*)d_in[15];
    const float* b2    = (const float*)d_in[16];

    float *t1, *mlp; unsigned* mask;
    __nv_bfloat16 *h_hi, *h_lo, *qkv_hi, *qkv_lo, *wqkv_hi, *wqkv_lo,
                  *wc_hi, *wc_lo, *w1_hi, *w1_lo, *ctx_hi, *ctx_lo, *t1_hi, *t1_lo;
    cudaGetSymbolAddress((void**)&t1,   g_t1);
    cudaGetSymbolAddress((void**)&mlp,  g_mlp);
    cudaGetSymbolAddress((void**)&mask, g_mask);
    cudaGetSymbolAddress((void**)&h_hi, g_h_hi);     cudaGetSymbolAddress((void**)&h_lo, g_h_lo);
    cudaGetSymbolAddress((void**)&qkv_hi, g_qkv_hi); cudaGetSymbolAddress((void**)&qkv_lo, g_qkv_lo);
    cudaGetSymbolAddress((void**)&wqkv_hi, g_wqkv_hi); cudaGetSymbolAddress((void**)&wqkv_lo, g_wqkv_lo);
    cudaGetSymbolAddress((void**)&wc_hi, g_wc_hi);   cudaGetSymbolAddress((void**)&wc_lo, g_wc_lo);
    cudaGetSymbolAddress((void**)&w1_hi, g_w1_hi);   cudaGetSymbolAddress((void**)&w1_lo, g_w1_lo);
    cudaGetSymbolAddress((void**)&ctx_hi, g_ctx_hi); cudaGetSymbolAddress((void**)&ctx_lo, g_ctx_lo);
    cudaGetSymbolAddress((void**)&t1_hi, g_t1_hi);   cudaGetSymbolAddress((void**)&t1_lo, g_t1_lo);

    static cudaStream_t s_mask = nullptr, s_w = nullptr;
    static cudaEvent_t ev_fork = nullptr, ev_m0 = nullptr, ev_m1 = nullptr,
                       ev_w = nullptr, ev_h = nullptr, ev_B = nullptr;
    if (!s_mask) {
        cudaStreamCreateWithFlags(&s_mask, cudaStreamNonBlocking);
        cudaStreamCreateWithFlags(&s_w, cudaStreamNonBlocking);
        cudaEventCreateWithFlags(&ev_fork, cudaEventDisableTiming);
        cudaEventCreateWithFlags(&ev_m0, cudaEventDisableTiming);
        cudaEventCreateWithFlags(&ev_m1, cudaEventDisableTiming);
        cudaEventCreateWithFlags(&ev_w, cudaEventDisableTiming);
        cudaEventCreateWithFlags(&ev_h, cudaEventDisableTiming);
        cudaEventCreateWithFlags(&ev_B, cudaEventDisableTiming);
    }

    cudaFuncSetAttribute(attention_mma_kernel, cudaFuncAttributeMaxDynamicSharedMemorySize, AT_SMEM_BYTES);
    cudaFuncSetAttribute(mma_gemm_bf16_kernel, cudaFuncAttributeMaxDynamicSharedMemorySize, GSMEM_BYTES);

    // fork side streams
    cudaEventRecord(ev_fork, 0);
    cudaStreamWaitEvent(s_mask, ev_fork, 0);
    cudaStreamWaitEvent(s_w, ev_fork, 0);

    // mask halves on s_mask (half k gates attention half k)
    dropout_mask_kernel<<<(1u << 26) / 256, 256, 0, s_mask>>>(mask, 0u);
    cudaEventRecord(ev_m0, s_mask);
    dropout_mask_kernel<<<(1u << 26) / 256, 256, 0, s_mask>>>(mask, 1u << 26);
    cudaEventRecord(ev_m1, s_mask);

    // weight splits (one launch) on s_w; chain B follows on the same stream
    convert_all_kernel<<<8192, 256, 0, s_w>>>(Wq, Wk, Wv, Wc, W1,
        wqkv_hi, wqkv_lo, wc_hi, wc_lo, w1_hi, w1_lo);
    cudaEventRecord(ev_w, s_w);

    // embed (whole batch) on stream 0
    sgemm_split_kernel<<<dim3(8, 64), 256>>>(x, W_emb, b_emb, h_hi, h_lo, 8192, 1024, 64);
    cudaEventRecord(ev_h, 0);

    const size_t RO = 4096;   // row offset for chain B

    // ---------------- chain A: rows 0..4095, bh 0..63 (default stream) ----------------
    cudaStreamWaitEvent(0, ev_w, 0);
    mma_gemm_bf16_kernel<<<dim3(24, 32), 256, GSMEM_BYTES>>>(
        h_hi, h_lo, wqkv_hi, wqkv_lo, nullptr, nullptr, qkv_hi, qkv_lo, 4096, 3072, 1024, 0);
    cudaStreamWaitEvent(0, ev_m0, 0);
    attention_mma_kernel<<<dim3(16, 64), 256, AT_SMEM_BYTES>>>(
        qkv_hi, qkv_lo, mask, ctx_hi, ctx_lo, 0);
    mma_gemm_bf16_kernel<<<dim3(8, 32), 256, GSMEM_BYTES>>>(
        ctx_hi, ctx_lo, wc_hi, wc_lo, b_c, t1, nullptr, nullptr, 4096, 1024, 1024, 0);
    layernorm1024_split_kernel<<<4096, 256>>>(t1, ln1_g, ln1_b, t1_hi, t1_lo);
    mma_gemm_bf16_kernel<<<dim3(32, 32), 256, GSMEM_BYTES>>>(
        t1_hi, t1_lo, w1_hi, w1_lo, b1, mlp, nullptr, nullptr, 4096, 4096, 1024, 1);
    ln_mv_fused_kernel<<<4096, 256>>>(mlp, ln2_g, ln2_b, W2, b2, (float*)d_out);

    // ---------------- chain B: rows 4096..8191, bh 64..127 (on s_w after converts) ----------------
    cudaStreamWaitEvent(s_w, ev_h, 0);
    mma_gemm_bf16_kernel<<<dim3(24, 32), 256, GSMEM_BYTES, s_w>>>(
        h_hi + RO * 1024, h_lo + RO * 1024, wqkv_hi, wqkv_lo, nullptr, nullptr,
        qkv_hi + RO * 3072, qkv_lo + RO * 3072, 4096, 3072, 1024, 0);
    cudaStreamWaitEvent(s_w, ev_m1, 0);
    attention_mma_kernel<<<dim3(16, 64), 256, AT_SMEM_BYTES, s_w>>>(
        qkv_hi, qkv_lo, mask, ctx_hi, ctx_lo, 64);
    mma_gemm_bf16_kernel<<<dim3(8, 32), 256, GSMEM_BYTES, s_w>>>(
        ctx_hi + RO * 1024, ctx_lo + RO * 1024, wc_hi, wc_lo, b_c, t1 + RO * 1024,
        nullptr, nullptr, 4096, 1024, 1024, 0);
    layernorm1024_split_kernel<<<4096, 256, 0, s_w>>>(
        t1 + RO * 1024, ln1_g, ln1_b, t1_hi + RO * 1024, t1_lo + RO * 1024);
    mma_gemm_bf16_kernel<<<dim3(32, 32), 256, GSMEM_BYTES, s_w>>>(
        t1_hi + RO * 1024, t1_lo + RO * 1024, w1_hi, w1_lo, b1, mlp + RO * 4096,
        nullptr, nullptr, 4096, 4096, 1024, 1);
    ln_mv_fused_kernel<<<4096, 256, 0, s_w>>>(
        mlp + RO * 4096, ln2_g, ln2_b, W2, b2, (float*)d_out + RO);
    cudaEventRecord(ev_B, s_w);

    // join chain B back to stream 0
    cudaStreamWaitEvent(0, ev_B, 0);
}